// round 15
// baseline (speedup 1.0000x reference)
#include <cuda_runtime.h>
#include <cuda_fp16.h>
#include <cstdint>
#include <cstddef>

// ============================================================================
// MotionGenerator fused: masked-conv1d(stride2,reflect7,K15)+pool+leakyReLU
// via mma.sync.m16n8k16 fp16 single-term (Ah*Bh), fp32 accum.
// R15 = R14 champion + SPLIT-CTA HALVES: each t-half (4 warps) owns a private
// A window (71 rows/parity, 7-row overlap duplicated) and syncs only with a
// named barrier scoped to its 128 threads. Halves slip freely; window-load
// latency of one half is covered by the other half's MMAs.
// ============================================================================

#define NG 12
#define NSLOT 85

__constant__ int   cOff[NG + 1] = {0, 8, 19, 26, 35, 39, 48, 52, 61, 65, 74, 78, 85};
__constant__ int   cE0[NG] = {0, 1, 3, 4, 6, 8, 10, 12, 14, 16, 18, 20};
__constant__ int   cE1[NG] = {-1, 2, -1, 5, 7, 9, 11, 13, 15, 17, 19, -1};

__constant__ int cSlotG[NSLOT] = {
    0,0,0,0,0,0,0,0,
    1,1,1,1,1,1,1,1,1,1,1,
    2,2,2,2,2,2,2,
    3,3,3,3,3,3,3,3,3,
    4,4,4,4,
    5,5,5,5,5,5,5,5,5,
    6,6,6,6,
    7,7,7,7,7,7,7,7,7,
    8,8,8,8,
    9,9,9,9,9,9,9,9,9,
    10,10,10,10,
    11,11,11,11,11,11,11
};

__constant__ int cJ[NSLOT] = {
    0,1,2,12,13,16,17,20,
    0,1,2,3,4,5,8,9,12,16,20,
    1,2,3,4,5,8,9,
    1,2,3,4,5,6,7,8,9,
    4,5,6,7,
    1,2,3,4,5,8,9,10,11,
    8,9,10,11,
    0,1,12,13,14,15,16,17,20,
    12,13,14,15,
    0,1,12,13,16,17,18,19,20,
    16,17,18,19,
    0,1,2,12,13,16,17
};

__constant__ float cC0[NSLOT] = {
    1,1,1,1,1,1,1,1,
    0.5f,0.5f,0.5f,0.5f,0.5f,0.0f,0.5f,0.0f,0.5f,0.5f,0.5f,
    1,1,1,1,1,1,1,
    0.5f,0.5f,0.5f,0.5f,0.5f,0.5f,0.0f,0.5f,0.5f,
    0.5f,0.5f,0.5f,0.5f,
    0.5f,0.5f,0.5f,0.5f,0.5f,0.5f,0.5f,0.5f,0.0f,
    0.5f,0.5f,0.5f,0.5f,
    0.5f,0.5f,0.5f,0.5f,0.5f,0.0f,0.5f,0.5f,0.5f,
    0.5f,0.5f,0.5f,0.5f,
    0.5f,0.5f,0.5f,0.5f,0.5f,0.5f,0.5f,0.0f,0.5f,
    0.5f,0.5f,0.5f,0.5f,
    1,1,1,1,1,1,1
};

__constant__ float cC1[NSLOT] = {
    0,0,0,0,0,0,0,0,
    0.5f,0.5f,0.5f,0.5f,0.5f,0.5f,0.5f,0.5f,0.0f,0.0f,0.5f,
    0,0,0,0,0,0,0,
    0.0f,0.5f,0.5f,0.5f,0.5f,0.5f,0.5f,0.5f,0.0f,
    0.0f,0.5f,0.5f,0.5f,
    0.0f,0.5f,0.5f,0.5f,0.0f,0.5f,0.5f,0.5f,0.5f,
    0.0f,0.5f,0.5f,0.5f,
    0.5f,0.0f,0.5f,0.5f,0.5f,0.5f,0.5f,0.0f,0.5f,
    0.0f,0.5f,0.5f,0.5f,
    0.5f,0.0f,0.5f,0.0f,0.5f,0.5f,0.5f,0.5f,0.5f,
    0.0f,0.5f,0.5f,0.5f,
    0,0,0,0,0,0,0
};

// Folded weights, fp16, dense [s][k][oc=128][ci=64]
__device__ __align__(16) __half g_Wh[(size_t)NSLOT * 15 * 8192];

// ---------------------------------------------------------------------------
// smem (bytes):
//   [0,512)         pooled bias (128 f32)
//   [512,+40896)    A: [half(2)][parity(2)][q=71 rows][72 halves], pitch 144B
//   [41408,+73728)  B: 8 warps x 2 bufs x 4608B (warp-private)
// Epilogue reuses [512,...) as D staging [128][132 f32] (67584B).
// ---------------------------------------------------------------------------
#define AP     72
#define AROWSH 71
#define ASZH   (AROWSH * AP)            // 5112 halves per (half,parity)
#define AHALFB (2 * ASZH * 2)           // 20448 bytes per half (2 parities)
#define A_OFF  512
#define B_OFF  (A_OFF + 2 * AHALFB)     // 41408
#define BSLICE 4608
#define SMEM_BYTES (B_OFF + 8 * 2 * BSLICE)   // 115136

__device__ __forceinline__ uint32_t smem_u32(const void* p) {
    uint32_t a;
    asm("{ .reg .u64 t; cvta.to.shared.u64 t, %1; cvt.u32.u64 %0, t; }" : "=r"(a) : "l"(p));
    return a;
}

__device__ __forceinline__ void mma16816(float* d, const uint32_t* a,
                                         uint32_t b0, uint32_t b1) {
    asm volatile(
        "mma.sync.aligned.m16n8k16.row.col.f32.f16.f16.f32 "
        "{%0,%1,%2,%3}, {%4,%5,%6,%7}, {%8,%9}, {%0,%1,%2,%3};"
        : "+f"(d[0]), "+f"(d[1]), "+f"(d[2]), "+f"(d[3])
        : "r"(a[0]), "r"(a[1]), "r"(a[2]), "r"(a[3]), "r"(b0), "r"(b1));
}

__device__ __forceinline__ void ldmx4(uint32_t* r, uint32_t addr) {
    asm volatile("ldmatrix.sync.aligned.m8n8.x4.shared.b16 {%0,%1,%2,%3}, [%4];"
                 : "=r"(r[0]), "=r"(r[1]), "=r"(r[2]), "=r"(r[3]) : "r"(addr));
}

// pack two fp32 -> half2: low half = lo, high half = hi
__device__ __forceinline__ uint32_t pkh2(float hi, float lo) {
    uint32_t d;
    asm("cvt.rn.f16x2.f32 %0, %1, %2;" : "=r"(d) : "f"(hi), "f"(lo));
    return d;
}

#define HALF_BAR(h) asm volatile("bar.sync %0, 128;" :: "r"(1 + (h)) : "memory")

// ---------------------------------------------------------------------------
__global__ void prep_wc(const float* __restrict__ weight) {
    const int s  = blockIdx.x;
    const int oc = blockIdx.y;
    const int g  = cSlotG[s];
    const int j  = cJ[s];
    const float c0 = cC0[s], c1 = cC1[s];
    const int e0 = cE0[g], e1 = cE1[g];

    const float* __restrict__ w0 = weight + (size_t)(e0 * 128 + oc) * 20160 + (size_t)j * 960;
    const float* __restrict__ w1 = (e1 >= 0)
        ? weight + (size_t)(e1 * 128 + oc) * 20160 + (size_t)j * 960 : nullptr;

    for (int q = threadIdx.x; q < 960; q += blockDim.x) {
        float v = c0 * w0[q];
        if (w1) v += c1 * w1[q];
        const int ci = q / 15;
        const int k  = q - ci * 15;
        g_Wh[((size_t)(s * 15 + k) * 128 + oc) * 64 + ci] = __float2half_rn(v);
    }
}

// ---------------------------------------------------------------------------
// Main: 256 threads, 8 warps = 2 t-halves x 4 oc-slices; warp tile 64t x 32oc.
// ---------------------------------------------------------------------------
__global__ __launch_bounds__(256, 2)
void motion_hmma(const float* __restrict__ x,
                 const float* __restrict__ bias,
                 float* __restrict__ out) {
    extern __shared__ __align__(16) char smem[];
    float* sbias = reinterpret_cast<float*>(smem);
    const uint32_t Asm = smem_u32(smem + A_OFF);
    const uint32_t Bsm = smem_u32(smem + B_OFF);

    const int tid  = threadIdx.x;
    const int w    = tid >> 5;       // 0..7
    const int lane = tid & 31;

    const int tile = blockIdx.x;   // 0..15
    const int b    = blockIdx.y;   // 0..7
    const int g    = blockIdx.z;   // 0..11
    const int t0   = tile << 7;
    const bool interior = (tile >= 1) && (tile <= 14);

    const int h       = w >> 2;          // t-half 0/1 (t = 64h + 0..63)
    const int warp_on = (w & 3) * 32;    // oc slice (warp-private B)
    const uint32_t Bwarp = Bsm + (uint32_t)w * (2 * BSLICE);
    const uint32_t Ahalf = Asm + (uint32_t)h * AHALFB;
    // this half's window: positions pos = (2t0-7) + 128h + r, r in [0,142)
    const int hbase = 2 * t0 - 7 + 128 * h;

    if (tid < 128) {
        const int e0 = cE0[g], e1 = cE1[g];
        float bv = bias[e0 * 128 + tid];
        if (e1 >= 0) bv = 0.5f * (bv + bias[e1 * 128 + tid]);
        sbias[tid] = bv;
    }

    float acc[4][4][4];
#pragma unroll
    for (int mi = 0; mi < 4; ++mi)
#pragma unroll
        for (int ni = 0; ni < 4; ++ni)
#pragma unroll
            for (int q = 0; q < 4; ++q) acc[mi][ni][q] = 0.f;

    const int off0 = cOff[g];
    const int nj   = cOff[g + 1] - off0;
    const int nt   = nj * 15;

    // warp-private cp.async: this warp's 32-oc slice of tap n -> buf n&1
    auto issue = [&](int n) {
        const int s = off0 + n / 15;
        const int k = n - (n / 15) * 15;
        const __half* __restrict__ tb =
            g_Wh + (size_t)(s * 15 + k) * 8192 + (size_t)warp_on * 64;
        const uint32_t dbase = Bwarp + (uint32_t)(n & 1) * BSLICE;
#pragma unroll
        for (int i = 0; i < 8; ++i) {
            const int c   = lane + (i << 5);      // 0..255
            const int row = c >> 3;               // 0..31 (local oc)
            const int col = c & 7;                // 16B chunk
            const __half* src = tb + (size_t)row * 64 + col * 8;
            const uint32_t dst = dbase + row * 144 + col * 16;
            asm volatile("cp.async.cg.shared.global [%0], [%1], 16;"
                         :: "r"(dst), "l"(src) : "memory");
        }
        asm volatile("cp.async.commit_group;" ::: "memory");
    };

    issue(0);
    if (nt > 1) issue(1);

    // per-lane ldmatrix address components
    const uint32_t aoff = (uint32_t)(lane & 15) * 144 + ((lane >> 4) ? 16u : 0u);
    const uint32_t boff = (uint32_t)(((lane >> 4) & 1) * 8 + (lane & 7)) * 144
                        + (((lane >> 3) & 1) ? 16u : 0u);   // local rows 0..15

    for (int jj = 0; jj < nj; ++jj) {
        const int j = cJ[off0 + jj];

        HALF_BAR(h);   // this half's warps done reading previous joint's window

        // ---- window load: x -> A[h][parity][q_local][ci], q_local = r>>1 ----
        const float* __restrict__ xj = x + ((size_t)b * 1344 + (size_t)j * 64) * 4096;
        if (interior) {
            // vector path, no reflection. Chunks cc'=0..35 cover r in [-1,142].
            // lane -> ci pair (2*lane, 2*lane+1); 4 warps stride chunks.
            const float* __restrict__ r0p =
                xj + (size_t)(2 * lane) * 4096 + (hbase - 1);   // pos of r=-1
            const float* __restrict__ r1p = r0p + 4096;
            uint32_t* __restrict__ Ae32 =
                reinterpret_cast<uint32_t*>(smem + A_OFF + h * AHALFB) + lane;
            uint32_t* __restrict__ Ao32 = Ae32 + (ASZH >> 1);   // +2556 u32
#pragma unroll
            for (int i = 0; i < 9; ++i) {
                const int cc = (w & 3) + 4 * i;                 // 0..35
                const float4 fa = *reinterpret_cast<const float4*>(r0p + 4 * cc);
                const float4 fb = *reinterpret_cast<const float4*>(r1p + 4 * cc);
                // chunk cc covers local r = 4cc-1 .. 4cc+2
                if (cc > 0)  Ao32[(size_t)(2 * cc - 1) * 36] = pkh2(fb.x, fa.x); // r=4cc-1
                Ae32[(size_t)(2 * cc    ) * 36] = pkh2(fb.y, fa.y);              // r=4cc
                Ao32[(size_t)(2 * cc    ) * 36] = pkh2(fb.z, fa.z);              // r=4cc+1
                if (cc < 35) Ae32[(size_t)(2 * cc + 1) * 36] = pkh2(fb.w, fa.w); // r=4cc+2
            }
        } else {
            // boundary path: scalar with reflection, local r in [0,142)
            __half* __restrict__ Ah = reinterpret_cast<__half*>(smem + A_OFF + h * AHALFB);
            for (int ci = (w & 3); ci < 64; ci += 4) {
                const float* __restrict__ src = xj + (size_t)ci * 4096;
                for (int r = lane; r < 142; r += 32) {
                    int pos = hbase + r;
                    pos = pos < 0 ? -pos : pos;
                    pos = pos > 4095 ? 8190 - pos : pos;
                    Ah[(size_t)(r & 1) * ASZH + (r >> 1) * AP + ci] =
                        __float2half_rn(src[pos]);
                }
            }
        }
        HALF_BAR(h);   // window visible to this half's 4 warps

        // ---- 15 taps, no CTA-wide barriers (B warp-private, A half-private) ----
        for (int k = 0; k < 15; ++k) {
            const int n = jj * 15 + k;

            if (n + 1 < nt) {
                asm volatile("cp.async.wait_group 1;" ::: "memory");
            } else {
                asm volatile("cp.async.wait_group 0;" ::: "memory");
            }

            const uint32_t Ap = Ahalf + (uint32_t)(k & 1) * (ASZH * 2)
                              + (uint32_t)(k >> 1) * 144 + aoff;
            const uint32_t Bp = Bwarp + (uint32_t)(n & 1) * BSLICE + boff;

#pragma unroll
            for (int cc = 0; cc < 4; ++cc) {
                uint32_t a[4][4];
#pragma unroll
                for (int mi = 0; mi < 4; ++mi)
                    ldmx4(a[mi], Ap + cc * 32 + mi * (16 * 144));
#pragma unroll
                for (int p = 0; p < 2; ++p) {
                    uint32_t bb[4];
                    ldmx4(bb, Bp + cc * 32 + p * (16 * 144));
#pragma unroll
                    for (int mi = 0; mi < 4; ++mi) {
                        mma16816(acc[mi][2 * p],     a[mi], bb[0], bb[1]);
                        mma16816(acc[mi][2 * p + 1], a[mi], bb[2], bb[3]);
                    }
                }
            }

            if (n + 2 < nt) issue(n + 2);   // refill ring (warp-private)
        }
    }

    __syncthreads();   // both halves done before staging overwrites A/B regions

    // ---- epilogue: transpose D via smem, bias + leaky relu ----
    float* Ds = reinterpret_cast<float*>(smem + A_OFF);   // [oc=128][pitch 132]
    {
        const int grow = lane >> 2;
        const int colb = (lane & 3) * 2;
#pragma unroll
        for (int mi = 0; mi < 4; ++mi) {
            const int row = 64 * h + mi * 16 + grow;       // global t in tile
#pragma unroll
            for (int ni = 0; ni < 4; ++ni) {
                const int col = warp_on + ni * 8 + colb;
                Ds[(col    ) * 132 + row    ] = acc[mi][ni][0];
                Ds[(col + 1) * 132 + row    ] = acc[mi][ni][1];
                Ds[(col    ) * 132 + row + 8] = acc[mi][ni][2];
                Ds[(col + 1) * 132 + row + 8] = acc[mi][ni][3];
            }
        }
    }
    __syncthreads();

    {
        const int oc = tid >> 1, half = tid & 1;
        const float bv = sbias[oc];
        const float4* __restrict__ sp =
            reinterpret_cast<const float4*>(Ds + oc * 132 + half * 64);
        float4* __restrict__ op = reinterpret_cast<float4*>(
            out + ((size_t)b * 1536 + (size_t)g * 128 + oc) * 2048 + t0 + half * 64);
#pragma unroll
        for (int i = 0; i < 16; ++i) {
            float4 v = sp[i];
            v.x += bv; v.y += bv; v.z += bv; v.w += bv;
            v.x = v.x > 0.f ? v.x : 0.2f * v.x;
            v.y = v.y > 0.f ? v.y : 0.2f * v.y;
            v.z = v.z > 0.f ? v.z : 0.2f * v.z;
            v.w = v.w > 0.f ? v.w : 0.2f * v.w;
            op[i] = v;
        }
    }
}

// ---------------------------------------------------------------------------
extern "C" void kernel_launch(void* const* d_in, const int* in_sizes, int n_in,
                              void* d_out, int out_size) {
    (void)in_sizes; (void)n_in; (void)out_size;
    const float* x      = (const float*)d_in[0];   // [8][1344][4096]
    const float* weight = (const float*)d_in[1];   // [2688][1344][15]
    const float* bias   = (const float*)d_in[2];   // [2688]
    float* out          = (float*)d_out;           // [8][1536][2048]

    cudaFuncSetAttribute(motion_hmma, cudaFuncAttributeMaxDynamicSharedMemorySize,
                         SMEM_BYTES);

    dim3 gp(NSLOT, 128);
    prep_wc<<<gp, 256>>>(weight);

    dim3 gm(16, 8, NG);
    motion_hmma<<<gm, 256, SMEM_BYTES>>>(x, bias, out);
}

// round 16
// speedup vs baseline: 1.1766x; 1.1766x over previous
#include <cuda_runtime.h>
#include <cuda_fp16.h>
#include <cstdint>
#include <cstddef>

// ============================================================================
// MotionGenerator fused: masked-conv1d(stride2,reflect7,K15)+pool+leakyReLU
// via mma.sync.m16n8k16 fp16 single-term (Ah*Bh), fp32 accum.
// R16 = R14 champion (warp-private B rings, vectorized window loader)
//       + LPT group ordering: launch groups longest-first (gOrder) so the
//         final scheduling wave is filled by the shortest CTAs.
// ============================================================================

#define NG 12
#define NSLOT 85

__constant__ int   cOff[NG + 1] = {0, 8, 19, 26, 35, 39, 48, 52, 61, 65, 74, 78, 85};
__constant__ int   cE0[NG] = {0, 1, 3, 4, 6, 8, 10, 12, 14, 16, 18, 20};
__constant__ int   cE1[NG] = {-1, 2, -1, 5, 7, 9, 11, 13, 15, 17, 19, -1};

// launch order: nj = {8,11,7,9,4,9,4,9,4,9,4,7} -> descending nj
__constant__ int gOrder[NG] = {1, 3, 5, 7, 9, 0, 2, 11, 4, 6, 8, 10};

__constant__ int cSlotG[NSLOT] = {
    0,0,0,0,0,0,0,0,
    1,1,1,1,1,1,1,1,1,1,1,
    2,2,2,2,2,2,2,
    3,3,3,3,3,3,3,3,3,
    4,4,4,4,
    5,5,5,5,5,5,5,5,5,
    6,6,6,6,
    7,7,7,7,7,7,7,7,7,
    8,8,8,8,
    9,9,9,9,9,9,9,9,9,
    10,10,10,10,
    11,11,11,11,11,11,11
};

__constant__ int cJ[NSLOT] = {
    0,1,2,12,13,16,17,20,
    0,1,2,3,4,5,8,9,12,16,20,
    1,2,3,4,5,8,9,
    1,2,3,4,5,6,7,8,9,
    4,5,6,7,
    1,2,3,4,5,8,9,10,11,
    8,9,10,11,
    0,1,12,13,14,15,16,17,20,
    12,13,14,15,
    0,1,12,13,16,17,18,19,20,
    16,17,18,19,
    0,1,2,12,13,16,17
};

__constant__ float cC0[NSLOT] = {
    1,1,1,1,1,1,1,1,
    0.5f,0.5f,0.5f,0.5f,0.5f,0.0f,0.5f,0.0f,0.5f,0.5f,0.5f,
    1,1,1,1,1,1,1,
    0.5f,0.5f,0.5f,0.5f,0.5f,0.5f,0.0f,0.5f,0.5f,
    0.5f,0.5f,0.5f,0.5f,
    0.5f,0.5f,0.5f,0.5f,0.5f,0.5f,0.5f,0.5f,0.0f,
    0.5f,0.5f,0.5f,0.5f,
    0.5f,0.5f,0.5f,0.5f,0.5f,0.0f,0.5f,0.5f,0.5f,
    0.5f,0.5f,0.5f,0.5f,
    0.5f,0.5f,0.5f,0.5f,0.5f,0.5f,0.5f,0.0f,0.5f,
    0.5f,0.5f,0.5f,0.5f,
    1,1,1,1,1,1,1
};

__constant__ float cC1[NSLOT] = {
    0,0,0,0,0,0,0,0,
    0.5f,0.5f,0.5f,0.5f,0.5f,0.5f,0.5f,0.5f,0.0f,0.0f,0.5f,
    0,0,0,0,0,0,0,
    0.0f,0.5f,0.5f,0.5f,0.5f,0.5f,0.5f,0.5f,0.0f,
    0.0f,0.5f,0.5f,0.5f,
    0.0f,0.5f,0.5f,0.5f,0.0f,0.5f,0.5f,0.5f,0.5f,
    0.0f,0.5f,0.5f,0.5f,
    0.5f,0.0f,0.5f,0.5f,0.5f,0.5f,0.5f,0.0f,0.5f,
    0.0f,0.5f,0.5f,0.5f,
    0.5f,0.0f,0.5f,0.0f,0.5f,0.5f,0.5f,0.5f,0.5f,
    0.0f,0.5f,0.5f,0.5f,
    0,0,0,0,0,0,0
};

// Folded weights, fp16, dense [s][k][oc=128][ci=64]
__device__ __align__(16) __half g_Wh[(size_t)NSLOT * 15 * 8192];

// ---------------------------------------------------------------------------
// smem (bytes):
//   [0,512)        pooled bias (128 f32)
//   [512,+39168)   A: [parity(2)][q=136][72 halves], pitch 144B (shared)
//   [39680,+73728) B: 8 warps x 2 bufs x 4608B (warp-private)
// Epilogue reuses [512,...) as D staging [128][132 f32] (67584B).
// ---------------------------------------------------------------------------
#define AP    72
#define AROWS 136
#define ASZ   (AROWS * AP)             // 9792 halves per parity
#define A_OFF 512
#define B_OFF (A_OFF + 2 * ASZ * 2)    // 39680
#define BSLICE 4608                    // 32 rows * 144 B
#define SMEM_BYTES (B_OFF + 8 * 2 * BSLICE)   // 113408

__device__ __forceinline__ uint32_t smem_u32(const void* p) {
    uint32_t a;
    asm("{ .reg .u64 t; cvta.to.shared.u64 t, %1; cvt.u32.u64 %0, t; }" : "=r"(a) : "l"(p));
    return a;
}

__device__ __forceinline__ void mma16816(float* d, const uint32_t* a,
                                         uint32_t b0, uint32_t b1) {
    asm volatile(
        "mma.sync.aligned.m16n8k16.row.col.f32.f16.f16.f32 "
        "{%0,%1,%2,%3}, {%4,%5,%6,%7}, {%8,%9}, {%0,%1,%2,%3};"
        : "+f"(d[0]), "+f"(d[1]), "+f"(d[2]), "+f"(d[3])
        : "r"(a[0]), "r"(a[1]), "r"(a[2]), "r"(a[3]), "r"(b0), "r"(b1));
}

__device__ __forceinline__ void ldmx4(uint32_t* r, uint32_t addr) {
    asm volatile("ldmatrix.sync.aligned.m8n8.x4.shared.b16 {%0,%1,%2,%3}, [%4];"
                 : "=r"(r[0]), "=r"(r[1]), "=r"(r[2]), "=r"(r[3]) : "r"(addr));
}

// pack two fp32 -> half2: low half = lo, high half = hi
__device__ __forceinline__ uint32_t pkh2(float hi, float lo) {
    uint32_t d;
    asm("cvt.rn.f16x2.f32 %0, %1, %2;" : "=r"(d) : "f"(hi), "f"(lo));
    return d;
}

// ---------------------------------------------------------------------------
__global__ void prep_wc(const float* __restrict__ weight) {
    const int s  = blockIdx.x;
    const int oc = blockIdx.y;
    const int g  = cSlotG[s];
    const int j  = cJ[s];
    const float c0 = cC0[s], c1 = cC1[s];
    const int e0 = cE0[g], e1 = cE1[g];

    const float* __restrict__ w0 = weight + (size_t)(e0 * 128 + oc) * 20160 + (size_t)j * 960;
    const float* __restrict__ w1 = (e1 >= 0)
        ? weight + (size_t)(e1 * 128 + oc) * 20160 + (size_t)j * 960 : nullptr;

    for (int q = threadIdx.x; q < 960; q += blockDim.x) {
        float v = c0 * w0[q];
        if (w1) v += c1 * w1[q];
        const int ci = q / 15;
        const int k  = q - ci * 15;
        g_Wh[((size_t)(s * 15 + k) * 128 + oc) * 64 + ci] = __float2half_rn(v);
    }
}

// ---------------------------------------------------------------------------
// Main: 256 threads, 8 warps (2 t-groups x 4 oc-slices), warp tile 64t x 32oc.
// ---------------------------------------------------------------------------
__global__ __launch_bounds__(256, 2)
void motion_hmma(const float* __restrict__ x,
                 const float* __restrict__ bias,
                 float* __restrict__ out) {
    extern __shared__ __align__(16) char smem[];
    float* sbias = reinterpret_cast<float*>(smem);
    __half* Aarr = reinterpret_cast<__half*>(smem + A_OFF);
    const uint32_t Asm = smem_u32(Aarr);
    const uint32_t Bsm = smem_u32(smem + B_OFF);

    const int tid  = threadIdx.x;
    const int w    = tid >> 5;       // 0..7
    const int lane = tid & 31;

    const int tile = blockIdx.x;         // 0..15
    const int b    = blockIdx.y;         // 0..7
    const int g    = gOrder[blockIdx.z]; // LPT: longest groups launch first
    const int t0   = tile << 7;
    const int base = 2 * t0 - 7;
    const bool interior = (tile >= 1) && (tile <= 14);

    const int warp_tm = (w & 1) * 64;    // t offset (64 rows)
    const int warp_on = (w >> 1) * 32;   // oc offset (32 cols, warp-private)
    const uint32_t Bwarp = Bsm + (uint32_t)w * (2 * BSLICE);

    if (tid < 128) {
        const int e0 = cE0[g], e1 = cE1[g];
        float bv = bias[e0 * 128 + tid];
        if (e1 >= 0) bv = 0.5f * (bv + bias[e1 * 128 + tid]);
        sbias[tid] = bv;
    }

    float acc[4][4][4];
#pragma unroll
    for (int mi = 0; mi < 4; ++mi)
#pragma unroll
        for (int ni = 0; ni < 4; ++ni)
#pragma unroll
            for (int q = 0; q < 4; ++q) acc[mi][ni][q] = 0.f;

    const int off0 = cOff[g];
    const int nj   = cOff[g + 1] - off0;
    const int nt   = nj * 15;

    // warp-private cp.async: this warp's 32-oc slice of tap n -> buf n&1
    auto issue = [&](int n) {
        const int s = off0 + n / 15;
        const int k = n - (n / 15) * 15;
        const __half* __restrict__ tb =
            g_Wh + (size_t)(s * 15 + k) * 8192 + (size_t)warp_on * 64;
        const uint32_t dbase = Bwarp + (uint32_t)(n & 1) * BSLICE;
#pragma unroll
        for (int i = 0; i < 8; ++i) {
            const int c   = lane + (i << 5);      // 0..255
            const int row = c >> 3;               // 0..31 (local oc)
            const int col = c & 7;                // 16B chunk
            const __half* src = tb + (size_t)row * 64 + col * 8;
            const uint32_t dst = dbase + row * 144 + col * 16;
            asm volatile("cp.async.cg.shared.global [%0], [%1], 16;"
                         :: "r"(dst), "l"(src) : "memory");
        }
        asm volatile("cp.async.commit_group;" ::: "memory");
    };

    issue(0);
    if (nt > 1) issue(1);

    // per-lane ldmatrix address components
    const uint32_t aoff = (uint32_t)(lane & 15) * 144 + ((lane >> 4) ? 16u : 0u);
    const uint32_t boff = (uint32_t)(((lane >> 4) & 1) * 8 + (lane & 7)) * 144
                        + (((lane >> 3) & 1) ? 16u : 0u);   // local rows 0..15

    for (int jj = 0; jj < nj; ++jj) {
        const int j = cJ[off0 + jj];

        __syncthreads();   // all warps done reading previous joint's A window

        // ---- window load: x -> A[parity][q][ci] fp16 (shared) ----
        const float* __restrict__ xj = x + ((size_t)b * 1344 + (size_t)j * 64) * 4096;
        if (interior) {
            // vector path: positions [2t0-8, 2t0+263], no reflection.
            const float* __restrict__ r0p = xj + (size_t)(2 * lane) * 4096 + (2 * t0 - 8);
            const float* __restrict__ r1p = r0p + 4096;
            uint32_t* __restrict__ Ae32 =
                reinterpret_cast<uint32_t*>(Aarr) + lane;              // row stride 36 u32
            uint32_t* __restrict__ Ao32 = Ae32 + (ASZ >> 1);
#pragma unroll
            for (int i = 0; i < 9; ++i) {
                const int c = w + 8 * i;
                if (c >= 68) break;
                const float4 fa = *reinterpret_cast<const float4*>(r0p + 4 * c);
                const float4 fb = *reinterpret_cast<const float4*>(r1p + 4 * c);
                if (c > 0) Ao32[(size_t)(2 * c - 1) * 36] = pkh2(fb.x, fa.x);  // r=4c-1
                Ae32[(size_t)(2 * c    ) * 36] = pkh2(fb.y, fa.y);             // r=4c
                Ao32[(size_t)(2 * c    ) * 36] = pkh2(fb.z, fa.z);             // r=4c+1
                Ae32[(size_t)(2 * c + 1) * 36] = pkh2(fb.w, fa.w);             // r=4c+2
            }
        } else {
            // boundary path: scalar with reflection
            for (int ci = w; ci < 64; ci += 8) {
                const float* __restrict__ src = xj + (size_t)ci * 4096;
                for (int r = lane; r < 269; r += 32) {
                    int pos = base + r;
                    pos = pos < 0 ? -pos : pos;
                    pos = pos > 4095 ? 8190 - pos : pos;
                    Aarr[(size_t)(r & 1) * ASZ + (r >> 1) * AP + ci] =
                        __float2half_rn(src[pos]);
                }
            }
        }
        __syncthreads();   // A visible to all warps

        // ---- 15 taps, NO CTA barriers: each warp free-runs its own B ring ----
        for (int k = 0; k < 15; ++k) {
            const int n = jj * 15 + k;

            if (n + 1 < nt) {
                asm volatile("cp.async.wait_group 1;" ::: "memory");   // group n done
            } else {
                asm volatile("cp.async.wait_group 0;" ::: "memory");
            }

            const uint32_t Ap = Asm + (uint32_t)(k & 1) * (ASZ * 2)
                              + (uint32_t)(warp_tm + (k >> 1)) * 144 + aoff;
            const uint32_t Bp = Bwarp + (uint32_t)(n & 1) * BSLICE + boff;

#pragma unroll
            for (int cc = 0; cc < 4; ++cc) {
                uint32_t a[4][4];
#pragma unroll
                for (int mi = 0; mi < 4; ++mi)
                    ldmx4(a[mi], Ap + cc * 32 + mi * (16 * 144));
#pragma unroll
                for (int p = 0; p < 2; ++p) {
                    uint32_t bb[4];
                    ldmx4(bb, Bp + cc * 32 + p * (16 * 144));
#pragma unroll
                    for (int mi = 0; mi < 4; ++mi) {
                        mma16816(acc[mi][2 * p],     a[mi], bb[0], bb[1]);
                        mma16816(acc[mi][2 * p + 1], a[mi], bb[2], bb[3]);
                    }
                }
            }

            // refill the ring AFTER this tap's LDSMs (warp-private WAR-safe)
            if (n + 2 < nt) issue(n + 2);
        }
    }

    __syncthreads();   // all MMAs done before staging overwrites A/B regions

    // ---- epilogue: transpose D via smem, bias + leaky relu ----
    float* Ds = reinterpret_cast<float*>(smem + A_OFF);   // [oc=128][pitch 132]
    {
        const int grow = lane >> 2;
        const int colb = (lane & 3) * 2;
#pragma unroll
        for (int mi = 0; mi < 4; ++mi) {
            const int row = warp_tm + mi * 16 + grow;
#pragma unroll
            for (int ni = 0; ni < 4; ++ni) {
                const int col = warp_on + ni * 8 + colb;
                Ds[(col    ) * 132 + row    ] = acc[mi][ni][0];
                Ds[(col + 1) * 132 + row    ] = acc[mi][ni][1];
                Ds[(col    ) * 132 + row + 8] = acc[mi][ni][2];
                Ds[(col + 1) * 132 + row + 8] = acc[mi][ni][3];
            }
        }
    }
    __syncthreads();

    {
        const int oc = tid >> 1, half = tid & 1;
        const float bv = sbias[oc];
        const float4* __restrict__ sp =
            reinterpret_cast<const float4*>(Ds + oc * 132 + half * 64);
        float4* __restrict__ op = reinterpret_cast<float4*>(
            out + ((size_t)b * 1536 + (size_t)g * 128 + oc) * 2048 + t0 + half * 64);
#pragma unroll
        for (int i = 0; i < 16; ++i) {
            float4 v = sp[i];
            v.x += bv; v.y += bv; v.z += bv; v.w += bv;
            v.x = v.x > 0.f ? v.x : 0.2f * v.x;
            v.y = v.y > 0.f ? v.y : 0.2f * v.y;
            v.z = v.z > 0.f ? v.z : 0.2f * v.z;
            v.w = v.w > 0.f ? v.w : 0.2f * v.w;
            op[i] = v;
        }
    }
}

// ---------------------------------------------------------------------------
extern "C" void kernel_launch(void* const* d_in, const int* in_sizes, int n_in,
                              void* d_out, int out_size) {
    (void)in_sizes; (void)n_in; (void)out_size;
    const float* x      = (const float*)d_in[0];   // [8][1344][4096]
    const float* weight = (const float*)d_in[1];   // [2688][1344][15]
    const float* bias   = (const float*)d_in[2];   // [2688]
    float* out          = (float*)d_out;           // [8][1536][2048]

    cudaFuncSetAttribute(motion_hmma, cudaFuncAttributeMaxDynamicSharedMemorySize,
                         SMEM_BYTES);

    dim3 gp(NSLOT, 128);
    prep_wc<<<gp, 256>>>(weight);

    dim3 gm(16, 8, NG);
    motion_hmma<<<gm, 256, SMEM_BYTES>>>(x, bias, out);
}